// round 2
// baseline (speedup 1.0000x reference)
#include <cuda_runtime.h>
#include <cuda_bf16.h>
#include <math.h>

// tril(A @ B), A and B lower-triangular, N=4096, fp32.
// Strategy: classic 128x128x16 shared-memory tiled SGEMM, 8x8 register tile
// per thread, but:
//   * only lower-triangular 128x128 blocks are launched (528 of 1024)
//   * per-block k-range clipped to [bj*128, (bi+1)*128)  (triangular inputs)
//   * inner product uses packed fma.rn.f32x2 (2 FMA per issue on sm_103a;
//     3-reg FFMA is half-rate rt=2, f32x2 recovers full fp32 throughput)
//   * blocks enumerated largest-K first for wave load balance
// Upper triangle of C zeroed with cudaMemsetAsync (graph-capturable).

#define NDIM 4096
#define BM 128
#define BN 128
#define BK 16
#define NB (NDIM / BM)  // 32

typedef unsigned long long ull;

__device__ __forceinline__ ull pack2(float lo, float hi) {
    ull r;
    asm("mov.b64 %0, {%1, %2};" : "=l"(r) : "f"(lo), "f"(hi));
    return r;
}

__device__ __forceinline__ void unpack2(ull v, float& lo, float& hi) {
    asm("mov.b64 {%0, %1}, %2;" : "=f"(lo), "=f"(hi) : "l"(v));
}

__device__ __forceinline__ void fma2(ull& d, ull a, ull b) {
    // d = a * b + d  on two packed fp32 lanes
    asm("fma.rn.f32x2 %0, %1, %2, %0;" : "+l"(d) : "l"(a), "l"(b));
}

__global__ __launch_bounds__(256, 2)
void trimm_kernel(const float* __restrict__ A,
                  const float* __restrict__ B,
                  float* __restrict__ C)
{
    // Shared tiles. As is stored transposed [k][m] with +8 float padding so
    // both the float4 loads stay 16B-aligned (136*4 = 544 = 34*16) and the
    // transposing scalar stores are bank-conflict-free.
    __shared__ __align__(16) float As[BK][BM + 8];
    __shared__ __align__(16) float Bs[BK][BN];

    // ---- map linear block id -> (bi, bj), largest diagonal distance first ----
    // Group g (g = 0..NB-1) has g+1 blocks and diagonal distance d = NB-1-g,
    // so the K=4096 corner block (31,0) is block 0 (starts earliest).
    int t = blockIdx.x;
    int g = (int)((sqrtf(8.0f * (float)t + 1.0f) - 1.0f) * 0.5f);
    while ((g + 1) * (g + 2) / 2 <= t) ++g;
    while (g * (g + 1) / 2 > t) --g;
    int off = t - g * (g + 1) / 2;
    int d  = (NB - 1) - g;
    int bj = off;
    int bi = bj + d;

    const int bm0 = bi * BM;
    const int bn0 = bj * BN;
    const int kStart = bn0;          // B[k, col] nonzero needs k >= col
    const int kEnd   = bm0 + BM;     // A[row, k] nonzero needs k <= row

    const int tid = threadIdx.x;
    const int tx = tid & 15;         // 0..15  -> column group
    const int ty = tid >> 4;         // 0..15  -> row group

    // global-load assignments
    const int arow  = tid >> 2;        // 0..63, +64 second half
    const int acol4 = (tid & 3) * 4;   // 0,4,8,12 within BK=16
    const int brow  = tid >> 5;        // 0..7, +8 second half
    const int bcol4 = (tid & 31) * 4;  // 0..124

    ull acc[8][4];
#pragma unroll
    for (int i = 0; i < 8; ++i)
#pragma unroll
        for (int j = 0; j < 4; ++j) acc[i][j] = 0ull;

    for (int k0 = kStart; k0 < kEnd; k0 += BK) {
        // ---- load A tile (transpose into As[k][m]) ----
#pragma unroll
        for (int h = 0; h < 2; ++h) {
            int r = arow + h * 64;
            float4 v = *(const float4*)&A[(size_t)(bm0 + r) * NDIM + k0 + acol4];
            As[acol4 + 0][r] = v.x;
            As[acol4 + 1][r] = v.y;
            As[acol4 + 2][r] = v.z;
            As[acol4 + 3][r] = v.w;
        }
        // ---- load B tile (direct copy, coalesced) ----
#pragma unroll
        for (int h = 0; h < 2; ++h) {
            int kr = brow + h * 8;
            *(float4*)&Bs[kr][bcol4] =
                *(const float4*)&B[(size_t)(k0 + kr) * NDIM + bn0 + bcol4];
        }
        __syncthreads();

#pragma unroll
        for (int k = 0; k < BK; ++k) {
            float4 a0 = *(const float4*)&As[k][ty * 4];
            float4 a1 = *(const float4*)&As[k][ty * 4 + 64];
            float4 b0 = *(const float4*)&Bs[k][tx * 4];
            float4 b1 = *(const float4*)&Bs[k][tx * 4 + 64];

            ull a2[8], b2[4];
            a2[0] = pack2(a0.x, a0.x);
            a2[1] = pack2(a0.y, a0.y);
            a2[2] = pack2(a0.z, a0.z);
            a2[3] = pack2(a0.w, a0.w);
            a2[4] = pack2(a1.x, a1.x);
            a2[5] = pack2(a1.y, a1.y);
            a2[6] = pack2(a1.z, a1.z);
            a2[7] = pack2(a1.w, a1.w);
            b2[0] = pack2(b0.x, b0.y);
            b2[1] = pack2(b0.z, b0.w);
            b2[2] = pack2(b1.x, b1.y);
            b2[3] = pack2(b1.z, b1.w);

#pragma unroll
            for (int i = 0; i < 8; ++i)
#pragma unroll
                for (int j = 0; j < 4; ++j)
                    fma2(acc[i][j], a2[i], b2[j]);
        }
        __syncthreads();
    }

    // ---- epilogue: masked stores (mask only bites on diagonal blocks) ----
#pragma unroll
    for (int i = 0; i < 8; ++i) {
        int r = bm0 + ty * 4 + (i & 3) + (i >> 2) * 64;
#pragma unroll
        for (int j = 0; j < 4; ++j) {
            int c = bn0 + tx * 4 + (j & 1) * 2 + (j >> 1) * 64;
            float lo, hi;
            unpack2(acc[i][j], lo, hi);
            if (c     <= r) C[(size_t)r * NDIM + c    ] = lo;
            if (c + 1 <= r) C[(size_t)r * NDIM + c + 1] = hi;
        }
    }
}

extern "C" void kernel_launch(void* const* d_in, const int* in_sizes, int n_in,
                              void* d_out, int out_size) {
    const float* A = (const float*)d_in[0];
    const float* B = (const float*)d_in[1];
    float* C = (float*)d_out;

    // Zero the whole output (upper triangle is never written by the kernel;
    // d_out is poisoned before timing). Async memset is graph-capturable.
    cudaMemsetAsync(C, 0, (size_t)NDIM * NDIM * sizeof(float), 0);

    const int nblocks = NB * (NB + 1) / 2;  // 528 lower-triangular tiles
    trimm_kernel<<<nblocks, 256>>>(A, B, C);
}

// round 4
// speedup vs baseline: 2.6111x; 2.6111x over previous
#include <cuda_runtime.h>
#include <cstdint>
#include <math.h>

// tril(A @ B), A,B lower-triangular fp32, N=4096.
// bf16 3-split GEMM on mma.sync.m16n8k16 (plain-ISA tensor path; tcgen05/TMA
// are unavailable: harness PTX target is sm_103 without the 'a' suffix).
//
// x = hi(bf16) + lo(bf16 of residual);  D = Ah*Bh + Al*Bh + Ah*Bl  (fp32 acc).
// 528 lower-triangular 128x128 tiles, k clipped to [bj*128,(bi+1)*128).
// BK=32 double-buffered smem; A tile [m][k] rows padded to 80B, B tile [k][n]
// with 16B-granule XOR swizzle, B frags via ldmatrix.x4.trans.

#define NDIM 4096
#define NB   32
#define BK   32
#define THREADS 256

#define A_ROWB 80              // 32 bf16 = 64B, padded to 80B (conflict-free)
#define ST_AH 0                // 128*80   = 10240
#define ST_AL 10240
#define ST_BH 20480            // 32*256   = 8192
#define ST_BL 28672
#define STAGE 36864
#define SMEM_DYN (2 * STAGE)   // 73728

static __device__ __forceinline__ uint32_t smem_u32(const void* p) {
    uint32_t a;
    asm("{ .reg .u64 t; cvta.to.shared.u64 t, %1; cvt.u32.u64 %0, t; }"
        : "=r"(a) : "l"(p));
    return a;
}

// pack two fp32 -> bf16x2, 'lo' in bits[15:0], 'hi' in bits[31:16]
static __device__ __forceinline__ uint32_t bf2(float lo, float hi) {
    uint32_t r;
    asm("cvt.rn.bf16x2.f32 %0, %1, %2;" : "=r"(r) : "f"(hi), "f"(lo));
    return r;
}

static __device__ __forceinline__ void ldm4(uint32_t d[4], uint32_t addr) {
    asm volatile("ldmatrix.sync.aligned.m8n8.x4.shared.b16 {%0,%1,%2,%3}, [%4];"
                 : "=r"(d[0]), "=r"(d[1]), "=r"(d[2]), "=r"(d[3]) : "r"(addr));
}
static __device__ __forceinline__ void ldm4t(uint32_t d[4], uint32_t addr) {
    asm volatile("ldmatrix.sync.aligned.m8n8.x4.trans.shared.b16 {%0,%1,%2,%3}, [%4];"
                 : "=r"(d[0]), "=r"(d[1]), "=r"(d[2]), "=r"(d[3]) : "r"(addr));
}

static __device__ __forceinline__ void mma16816(float* c, const uint32_t* a,
                                                const uint32_t* b) {
    asm volatile(
        "mma.sync.aligned.m16n8k16.row.col.f32.bf16.bf16.f32 "
        "{%0,%1,%2,%3}, {%4,%5,%6,%7}, {%8,%9}, {%0,%1,%2,%3};"
        : "+f"(c[0]), "+f"(c[1]), "+f"(c[2]), "+f"(c[3])
        : "r"(a[0]), "r"(a[1]), "r"(a[2]), "r"(a[3]), "r"(b[0]), "r"(b[1]));
}

// split one float4 into hi/lo bf16x2 pairs
static __device__ __forceinline__ void split4(float4 v, uint32_t& h01, uint32_t& h23,
                                              uint32_t& l01, uint32_t& l23) {
    h01 = bf2(v.x, v.y);
    h23 = bf2(v.z, v.w);
    float r0 = v.x - __uint_as_float(h01 << 16);
    float r1 = v.y - __uint_as_float(h01 & 0xFFFF0000u);
    float r2 = v.z - __uint_as_float(h23 << 16);
    float r3 = v.w - __uint_as_float(h23 & 0xFFFF0000u);
    l01 = bf2(r0, r1);
    l23 = bf2(r2, r3);
}

static __device__ __forceinline__ void sts2(uint32_t addr, uint32_t a, uint32_t b) {
    asm volatile("st.shared.v2.b32 [%0], {%1,%2};" :: "r"(addr), "r"(a), "r"(b)
                 : "memory");
}

__global__ __launch_bounds__(THREADS, 1)
void trimm_mma(const float* __restrict__ A, const float* __restrict__ B,
               float* __restrict__ C)
{
    extern __shared__ __align__(128) char dyn_smem[];
    const uint32_t sbase = smem_u32(dyn_smem);

    const int tid  = threadIdx.x;
    const int wid  = tid >> 5;
    const int lane = tid & 31;

    // ---- block id -> (bi,bj), largest-K first ----
    int t = blockIdx.x;
    int g = (int)((sqrtf(8.0f * (float)t + 1.0f) - 1.0f) * 0.5f);
    while ((g + 1) * (g + 2) / 2 <= t) ++g;
    while (g * (g + 1) / 2 > t) --g;
    const int bj = t - g * (g + 1) / 2;
    const int bi = bj + (NB - 1) - g;
    const int bm0 = bi * 128, bn0 = bj * 128;
    const int kStart = bn0, kEnd = bm0 + 128;
    const int nchunks = (kEnd - kStart) >> 5;    // 4..128

    // warp tile: 2(m) x 4(n) warp grid, 64x32 per warp
    const int m0w = (wid & 1) * 64;
    const int n0w = (wid >> 1) * 32;

    // per-lane ldmatrix address components
    const uint32_t laneA    = (uint32_t)((lane & 15) * A_ROWB + ((lane >> 4) << 4));
    const uint32_t laneBRow = (uint32_t)((lane & 15) * 256);
    const uint32_t laneBCol = (uint32_t)((((lane >> 4) ^ (lane & 7)) << 4));

    // global load indices
    const int amRow = tid >> 3;            // 0..31 (+32 per pass)
    const int akOff = (tid & 7) * 4;       // k offset (floats)
    const int bkRow = tid >> 5;            // 0..7 (+8 per pass)
    const int bnOff = (tid & 31) * 4;      // n offset (floats)

    float acc[4][4][4];
#pragma unroll
    for (int mt = 0; mt < 4; ++mt)
#pragma unroll
        for (int nt = 0; nt < 4; ++nt)
#pragma unroll
            for (int e = 0; e < 4; ++e) acc[mt][nt][e] = 0.0f;

    float4 ra[4], rb[4];

    // ---- load chunk k0 into registers ----
#define LOAD_CHUNK(k0)                                                          \
    {                                                                           \
        _Pragma("unroll")                                                       \
        for (int p = 0; p < 4; ++p) {                                           \
            ra[p] = *(const float4*)(A + (size_t)(bm0 + amRow + p * 32) * NDIM  \
                                       + (k0) + akOff);                         \
            rb[p] = *(const float4*)(B + (size_t)((k0) + bkRow + p * 8) * NDIM  \
                                       + bn0 + bnOff);                          \
        }                                                                       \
    }

    // ---- convert regs -> smem stage ----
#define STORE_CHUNK(sbuf)                                                       \
    {                                                                           \
        _Pragma("unroll")                                                       \
        for (int p = 0; p < 4; ++p) {                                           \
            uint32_t h01, h23, l01, l23;                                        \
            split4(ra[p], h01, h23, l01, l23);                                  \
            uint32_t aoff = (uint32_t)((amRow + p * 32) * A_ROWB + akOff * 2);  \
            sts2((sbuf) + ST_AH + aoff, h01, h23);                              \
            sts2((sbuf) + ST_AL + aoff, l01, l23);                              \
            split4(rb[p], h01, h23, l01, l23);                                  \
            int kk = bkRow + p * 8;                                             \
            uint32_t boff = (uint32_t)(kk * 256 +                               \
                            ((bnOff * 2) ^ ((kk & 7) << 4)));                   \
            sts2((sbuf) + ST_BH + boff, h01, h23);                              \
            sts2((sbuf) + ST_BL + boff, l01, l23);                              \
        }                                                                       \
    }

    // prologue
    LOAD_CHUNK(kStart);
    STORE_CHUNK(sbase);
    __syncthreads();

    for (int c = 0; c < nchunks; ++c) {
        const uint32_t scur = sbase + (uint32_t)(c & 1) * STAGE;
        const bool more = (c + 1 < nchunks);
        if (more) LOAD_CHUNK(kStart + (c + 1) * BK);

        // ---- compute on current stage ----
#pragma unroll
        for (int ks = 0; ks < BK; ks += 16) {
            uint32_t aH[4][4], aL[4][4], bH[2][4], bL[2][4];
#pragma unroll
            for (int mt = 0; mt < 4; ++mt) {
                uint32_t ar = scur + ST_AH +
                              (uint32_t)((m0w + 16 * mt) * A_ROWB + ks * 2) + laneA;
                ldm4(aH[mt], ar);
                ldm4(aL[mt], ar + (ST_AL - ST_AH));
            }
#pragma unroll
            for (int ntp = 0; ntp < 2; ++ntp) {
                uint32_t twoN0 = (uint32_t)((n0w + 16 * ntp) * 2);
                uint32_t br = scur + ST_BH + (uint32_t)(ks * 256) + laneBRow +
                              (twoN0 ^ laneBCol);
                ldm4t(bH[ntp], br);
                ldm4t(bL[ntp], br + (ST_BL - ST_BH));
            }
#pragma unroll
            for (int mt = 0; mt < 4; ++mt)
#pragma unroll
                for (int nt = 0; nt < 4; ++nt) {
                    const uint32_t* bh = &bH[nt >> 1][(nt & 1) * 2];
                    const uint32_t* bl = &bL[nt >> 1][(nt & 1) * 2];
                    mma16816(acc[mt][nt], aH[mt], bh);
                    mma16816(acc[mt][nt], aL[mt], bh);
                    mma16816(acc[mt][nt], aH[mt], bl);
                }
        }

        if (more) STORE_CHUNK(sbase + (uint32_t)((c + 1) & 1) * STAGE);
        __syncthreads();
    }

    // ---- epilogue: tril-masked stores ----
#pragma unroll
    for (int mt = 0; mt < 4; ++mt) {
        const int r0 = bm0 + m0w + 16 * mt + (lane >> 2);
#pragma unroll
        for (int nt = 0; nt < 4; ++nt) {
            const int c0 = bn0 + n0w + 8 * nt + 2 * (lane & 3);
            float* p0 = C + (size_t)r0 * NDIM + c0;
            float* p1 = p0 + 8 * (size_t)NDIM;
            if (c0     <= r0)     p0[0] = acc[mt][nt][0];
            if (c0 + 1 <= r0)     p0[1] = acc[mt][nt][1];
            if (c0     <= r0 + 8) p1[0] = acc[mt][nt][2];
            if (c0 + 1 <= r0 + 8) p1[1] = acc[mt][nt][3];
        }
    }
}

extern "C" void kernel_launch(void* const* d_in, const int* in_sizes, int n_in,
                              void* d_out, int out_size) {
    const float* A = (const float*)d_in[0];
    const float* B = (const float*)d_in[1];
    float* C = (float*)d_out;

    cudaFuncSetAttribute(trimm_mma, cudaFuncAttributeMaxDynamicSharedMemorySize,
                         SMEM_DYN);

    // zero output (kernel never writes the strict upper triangle)
    cudaMemsetAsync(C, 0, (size_t)NDIM * NDIM * sizeof(float), 0);

    const int nblocks = NB * (NB + 1) / 2;   // 528
    trimm_mma<<<nblocks, THREADS, SMEM_DYN>>>(A, B, C);
}

// round 5
// speedup vs baseline: 2.7671x; 1.0597x over previous
#include <cuda_runtime.h>
#include <cstdint>
#include <math.h>

// tril(A @ B), A,B lower-triangular fp32, N=4096.
// bf16 3-split GEMM on mma.sync.m16n8k16 (tcgen05/TMA unavailable: harness
// PTX target is sm_103 without 'a').
//
// R5: 128x64 C tiles (2 half-tiles per 128x128 block, 1056 CTAs) so that
// acc regs halve and 2 CTAs co-reside per SM (occ 12.5% -> 25%), hiding
// HMMA/ldmatrix latency and __syncthreads. Per-half k clipping:
// kStart = column start of the half; kEnd = (bi+1)*128.

#define NDIM 4096
#define NB   32
#define BK   32
#define THREADS 256

#define A_ROWB 80              // 32 bf16 = 64B padded to 80B
#define ST_AH 0                // 128*80 = 10240
#define ST_AL 10240
#define ST_BH 20480            // 32 k-rows * 128B = 4096
#define ST_BL 24576
#define STAGE 28672
#define SMEM_DYN (2 * STAGE)   // 57344 -> 2 CTAs/SM = 114688 < 228KB

static __device__ __forceinline__ uint32_t smem_u32(const void* p) {
    uint32_t a;
    asm("{ .reg .u64 t; cvta.to.shared.u64 t, %1; cvt.u32.u64 %0, t; }"
        : "=r"(a) : "l"(p));
    return a;
}

// pack two fp32 -> bf16x2, 'lo' in bits[15:0], 'hi' in bits[31:16]
static __device__ __forceinline__ uint32_t bf2(float lo, float hi) {
    uint32_t r;
    asm("cvt.rn.bf16x2.f32 %0, %1, %2;" : "=r"(r) : "f"(hi), "f"(lo));
    return r;
}

static __device__ __forceinline__ void ldm4(uint32_t d[4], uint32_t addr) {
    asm volatile("ldmatrix.sync.aligned.m8n8.x4.shared.b16 {%0,%1,%2,%3}, [%4];"
                 : "=r"(d[0]), "=r"(d[1]), "=r"(d[2]), "=r"(d[3]) : "r"(addr));
}
static __device__ __forceinline__ void ldm4t(uint32_t d[4], uint32_t addr) {
    asm volatile("ldmatrix.sync.aligned.m8n8.x4.trans.shared.b16 {%0,%1,%2,%3}, [%4];"
                 : "=r"(d[0]), "=r"(d[1]), "=r"(d[2]), "=r"(d[3]) : "r"(addr));
}

static __device__ __forceinline__ void mma16816(float* c, const uint32_t* a,
                                                const uint32_t* b) {
    asm volatile(
        "mma.sync.aligned.m16n8k16.row.col.f32.bf16.bf16.f32 "
        "{%0,%1,%2,%3}, {%4,%5,%6,%7}, {%8,%9}, {%0,%1,%2,%3};"
        : "+f"(c[0]), "+f"(c[1]), "+f"(c[2]), "+f"(c[3])
        : "r"(a[0]), "r"(a[1]), "r"(a[2]), "r"(a[3]), "r"(b[0]), "r"(b[1]));
}

static __device__ __forceinline__ void split4(float4 v, uint32_t& h01, uint32_t& h23,
                                              uint32_t& l01, uint32_t& l23) {
    h01 = bf2(v.x, v.y);
    h23 = bf2(v.z, v.w);
    float r0 = v.x - __uint_as_float(h01 << 16);
    float r1 = v.y - __uint_as_float(h01 & 0xFFFF0000u);
    float r2 = v.z - __uint_as_float(h23 << 16);
    float r3 = v.w - __uint_as_float(h23 & 0xFFFF0000u);
    l01 = bf2(r0, r1);
    l23 = bf2(r2, r3);
}

static __device__ __forceinline__ void sts2(uint32_t addr, uint32_t a, uint32_t b) {
    asm volatile("st.shared.v2.b32 [%0], {%1,%2};" :: "r"(addr), "r"(a), "r"(b)
                 : "memory");
}

__global__ __launch_bounds__(THREADS, 2)
void trimm_mma(const float* __restrict__ A, const float* __restrict__ B,
               float* __restrict__ C)
{
    extern __shared__ __align__(128) char dyn_smem[];
    const uint32_t sbase = smem_u32(dyn_smem);

    const int tid  = threadIdx.x;
    const int wid  = tid >> 5;
    const int lane = tid & 31;

    // ---- block id -> (bi,bj,half), largest-K first ----
    const int bid  = blockIdx.x;
    const int t    = bid >> 1;
    const int half = bid & 1;
    int g = (int)((sqrtf(8.0f * (float)t + 1.0f) - 1.0f) * 0.5f);
    while ((g + 1) * (g + 2) / 2 <= t) ++g;
    while (g * (g + 1) / 2 > t) --g;
    const int bj = t - g * (g + 1) / 2;
    const int bi = bj + (NB - 1) - g;
    const int bm0 = bi * 128;
    const int bn0 = bj * 128 + half * 64;
    const int kStart = bn0;              // k >= col for B nonzero
    const int kEnd   = bm0 + 128;        // k <= row for A nonzero
    const int nchunks = (kEnd - kStart) >> 5;   // 2..128

    // warp grid: 4(m) x 2(n); warp tile 32x32
    const int m0w = (wid & 3) * 32;
    const int n0w = (wid >> 2) * 32;

    // ldmatrix lane address components
    const uint32_t laneA    = (uint32_t)((lane & 15) * A_ROWB + ((lane >> 4) << 4));
    const uint32_t laneBRow = (uint32_t)((lane & 15) * 128);
    const uint32_t laneBCol = (uint32_t)((((lane >> 4) ^ (lane & 7)) << 4));

    // global load indices
    const int amRow = tid >> 3;            // 0..31 (+32 per pass, 4 passes)
    const int akOff = (tid & 7) * 4;       // k float offset
    const int bkRow = tid >> 4;            // 0..15 (+16 per pass, 2 passes)
    const int bnOff = (tid & 15) * 4;      // n float offset (0..60)

    float acc[2][4][4];
#pragma unroll
    for (int mt = 0; mt < 2; ++mt)
#pragma unroll
        for (int nt = 0; nt < 4; ++nt)
#pragma unroll
            for (int e = 0; e < 4; ++e) acc[mt][nt][e] = 0.0f;

    float4 ra[4], rb[2];

#define LOAD_CHUNK(k0)                                                          \
    {                                                                           \
        _Pragma("unroll")                                                       \
        for (int p = 0; p < 4; ++p)                                             \
            ra[p] = *(const float4*)(A + (size_t)(bm0 + amRow + p * 32) * NDIM  \
                                       + (k0) + akOff);                         \
        _Pragma("unroll")                                                       \
        for (int p = 0; p < 2; ++p)                                             \
            rb[p] = *(const float4*)(B + (size_t)((k0) + bkRow + p * 16) * NDIM \
                                       + bn0 + bnOff);                          \
    }

#define STORE_CHUNK(sbuf)                                                       \
    {                                                                           \
        _Pragma("unroll")                                                       \
        for (int p = 0; p < 4; ++p) {                                           \
            uint32_t h01, h23, l01, l23;                                        \
            split4(ra[p], h01, h23, l01, l23);                                  \
            uint32_t aoff = (uint32_t)((amRow + p * 32) * A_ROWB + akOff * 2);  \
            sts2((sbuf) + ST_AH + aoff, h01, h23);                              \
            sts2((sbuf) + ST_AL + aoff, l01, l23);                              \
        }                                                                       \
        _Pragma("unroll")                                                       \
        for (int p = 0; p < 2; ++p) {                                           \
            uint32_t h01, h23, l01, l23;                                        \
            split4(rb[p], h01, h23, l01, l23);                                  \
            int kk = bkRow + p * 16;                                            \
            uint32_t boff = (uint32_t)(kk * 128 +                               \
                            ((bnOff * 2) ^ ((kk & 7) << 4)));                   \
            sts2((sbuf) + ST_BH + boff, h01, h23);                              \
            sts2((sbuf) + ST_BL + boff, l01, l23);                              \
        }                                                                       \
    }

    // prologue
    LOAD_CHUNK(kStart);
    STORE_CHUNK(sbase);
    __syncthreads();

    for (int c = 0; c < nchunks; ++c) {
        const uint32_t scur = sbase + (uint32_t)(c & 1) * STAGE;
        const bool more = (c + 1 < nchunks);
        if (more) LOAD_CHUNK(kStart + (c + 1) * BK);

#pragma unroll
        for (int ks = 0; ks < BK; ks += 16) {
            uint32_t aH[2][4], aL[2][4], bH[2][4], bL[2][4];
#pragma unroll
            for (int mt = 0; mt < 2; ++mt) {
                uint32_t ar = scur + ST_AH +
                              (uint32_t)((m0w + 16 * mt) * A_ROWB + ks * 2) + laneA;
                ldm4(aH[mt], ar);
                ldm4(aL[mt], ar + (ST_AL - ST_AH));
            }
#pragma unroll
            for (int ntp = 0; ntp < 2; ++ntp) {
                uint32_t twoN0 = (uint32_t)((n0w + 16 * ntp) * 2);
                uint32_t br = scur + ST_BH + (uint32_t)(ks * 128) + laneBRow +
                              (twoN0 ^ laneBCol);
                ldm4t(bH[ntp], br);
                ldm4t(bL[ntp], br + (ST_BL - ST_BH));
            }
#pragma unroll
            for (int mt = 0; mt < 2; ++mt)
#pragma unroll
                for (int nt = 0; nt < 4; ++nt) {
                    const uint32_t* bh = &bH[nt >> 1][(nt & 1) * 2];
                    const uint32_t* bl = &bL[nt >> 1][(nt & 1) * 2];
                    mma16816(acc[mt][nt], aH[mt], bh);
                    mma16816(acc[mt][nt], aL[mt], bh);
                    mma16816(acc[mt][nt], aH[mt], bl);
                }
        }

        if (more) STORE_CHUNK(sbase + (uint32_t)((c + 1) & 1) * STAGE);
        __syncthreads();
    }

    // ---- epilogue: tril-masked stores ----
#pragma unroll
    for (int mt = 0; mt < 2; ++mt) {
        const int r0 = bm0 + m0w + 16 * mt + (lane >> 2);
#pragma unroll
        for (int nt = 0; nt < 4; ++nt) {
            const int c0 = bn0 + n0w + 8 * nt + 2 * (lane & 3);
            float* p0 = C + (size_t)r0 * NDIM + c0;
            float* p1 = p0 + 8 * (size_t)NDIM;
            if (c0     <= r0)     p0[0] = acc[mt][nt][0];
            if (c0 + 1 <= r0)     p0[1] = acc[mt][nt][1];
            if (c0     <= r0 + 8) p1[0] = acc[mt][nt][2];
            if (c0 + 1 <= r0 + 8) p1[1] = acc[mt][nt][3];
        }
    }
}

extern "C" void kernel_launch(void* const* d_in, const int* in_sizes, int n_in,
                              void* d_out, int out_size) {
    const float* A = (const float*)d_in[0];
    const float* B = (const float*)d_in[1];
    float* C = (float*)d_out;

    cudaFuncSetAttribute(trimm_mma, cudaFuncAttributeMaxDynamicSharedMemorySize,
                         SMEM_DYN);

    // zero output (kernel never writes the strict upper triangle)
    cudaMemsetAsync(C, 0, (size_t)NDIM * NDIM * sizeof(float), 0);

    const int nblocks = NB * (NB + 1);   // 1056 half-tiles
    trimm_mma<<<nblocks, THREADS, SMEM_DYN>>>(A, B, C);
}